// round 15
// baseline (speedup 1.0000x reference)
#include <cuda_runtime.h>
#include <cuda_fp16.h>
#include <math.h>
#include <stdint.h>

#define HID   4096
#define NH    32
#define HD    128
#define HALF  64
#define BB    2
#define SS    2048
#define THID  12288
#define MTOK  (BB*SS)
#define SCALING 0.08838834764831845f

// ---------------- scratch ----------------------------------------------------
__device__ __half g_qkv_h[(size_t)MTOK * THID];
__device__ __half g_q_h [(size_t)MTOK * HID];
__device__ __half g_k_h [(size_t)MTOK * HID];
__device__ __half g_hid_h [(size_t)MTOK * HID];
__device__ __half g_attn_h[(size_t)MTOK * HID];
__device__ __half g_wqkv_h[(size_t)THID * HID];  // transposed [N][K]
__device__ __half g_wo_h  [(size_t)HID * HID];   // transposed [N][K]

// ---------------------------- asm helpers -----------------------------------
__device__ __forceinline__ uint32_t smem_u32(const void* p) {
    uint32_t a;
    asm("{ .reg .u64 t; cvta.to.shared.u64 t, %1; cvt.u32.u64 %0, t; }" : "=r"(a) : "l"(p));
    return a;
}
#define CP16(dst, src)  asm volatile("cp.async.cg.shared.global [%0], [%1], 16;" :: "r"(dst), "l"(src) : "memory")
#define CP_COMMIT()     asm volatile("cp.async.commit_group;" ::: "memory")
#define CP_WAIT1()      asm volatile("cp.async.wait_group 1;" ::: "memory")
#define CP_WAIT2()      asm volatile("cp.async.wait_group 2;" ::: "memory")

#define LDSM4(r0,r1,r2,r3,addr)                                                \
    asm volatile("ldmatrix.sync.aligned.m8n8.x4.shared.b16 {%0,%1,%2,%3}, [%4];" \
        : "=r"(r0),"=r"(r1),"=r"(r2),"=r"(r3) : "r"(addr))

#define LDSM4T(r0,r1,r2,r3,addr)                                               \
    asm volatile("ldmatrix.sync.aligned.m8n8.x4.trans.shared.b16 {%0,%1,%2,%3}, [%4];" \
        : "=r"(r0),"=r"(r1),"=r"(r2),"=r"(r3) : "r"(addr))

#define MMA16816(c,a,b0,b1)                                                    \
    asm volatile("mma.sync.aligned.m16n8k16.row.col.f32.f16.f16.f32 "          \
        "{%0,%1,%2,%3},{%4,%5,%6,%7},{%8,%9},{%0,%1,%2,%3};"                   \
        : "+f"((c)[0]),"+f"((c)[1]),"+f"((c)[2]),"+f"((c)[3])                  \
        : "r"((a)[0]),"r"((a)[1]),"r"((a)[2]),"r"((a)[3]),"r"(b0),"r"(b1))

// 128B-row swizzle (8 x 16B granules, XOR with row&7)
__device__ __forceinline__ uint32_t gswz(int row, int g) {
    return (uint32_t)(row * 128 + ((g ^ (row & 7)) << 4));
}
// 256B-row variant for the flash tiles.
__device__ __forceinline__ uint32_t vswz(int row, int g) {
    return (uint32_t)(row * 256 + ((g ^ (row & 7)) << 4));
}

// ---------------------------------------------------------------------------
__global__ __launch_bounds__(256) void convert_h(const float* __restrict__ in,
                                                 __half* __restrict__ hi, size_t n4) {
    size_t i = (size_t)blockIdx.x * blockDim.x + threadIdx.x;
    if (i >= n4) return;
    float4 v = ((const float4*)in)[i];
    __half h[4] = {__float2half(v.x), __float2half(v.y),
                   __float2half(v.z), __float2half(v.w)};
    ((uint2*)hi)[i] = *(uint2*)h;
}

// ---------------------------------------------------------------------------
// Transpose + fp16: B[K][N] fp32 -> Bt [N][K].  32k x 64n tiles.
// ---------------------------------------------------------------------------
__global__ __launch_bounds__(256) void transpose_h(const float* __restrict__ B,
                                                   __half* __restrict__ th,
                                                   int K, int N) {
    __shared__ float tile[32][65];
    const int n0 = blockIdx.x * 64, k0 = blockIdx.y * 32;
#pragma unroll
    for (int i = 0; i < 8; i++) {
        int idx = threadIdx.x + i * 256;
        int r = idx >> 6, c = idx & 63;
        tile[r][c] = B[(size_t)(k0 + r) * N + n0 + c];
    }
    __syncthreads();
#pragma unroll
    for (int i = 0; i < 4; i++) {
        int idx = threadIdx.x + i * 256;
        int n = idx >> 4, kp = idx & 15;
        __half2 v = __floats2half2_rn(tile[2 * kp][n], tile[2 * kp + 1][n]);
        *(__half2*)(th + (size_t)(n0 + n) * K + k0 + 2 * kp) = v;
    }
}

// ---------------------------------------------------------------------------
// Persistent fp16 GEMM. 128x256 CTA tile, warp tile 64x64 (2x4 warps),
// BK=64, 3 stages x 48KB, 1 CTA/SM (256 regs budget).
// ---------------------------------------------------------------------------
#define ABUF  16384                // A: 128 rows x 128B
#define BBUF  32768                // B: 256 rows x 128B
#define STGB  (ABUF + BBUF)        // 48KB
#define NSTG  3
#define GEMM_DYN (NSTG * STGB)

__device__ __forceinline__ void stage_copies(int tid, int m0, int n0, int kc, int K,
                                             uint32_t sbase,
                                             const __half* Ah, const __half* Bh) {
#pragma unroll
    for (int i = 0; i < 12; i++) {
        int id = tid + i * 256;        // 0..3071
        if (id < 1024) {               // A: 128 rows x 8 granules
            int row = id >> 3, g = id & 7;
            CP16(sbase + gswz(row, g),
                 Ah + (size_t)(m0 + row) * K + kc + g * 8);
        } else {                       // B: 256 rows x 8 granules
            int idx = id - 1024;
            int row = idx >> 3, g = idx & 7;
            CP16(sbase + ABUF + gswz(row, g),
                 Bh + (size_t)(n0 + row) * K + kc + g * 8);
        }
    }
    CP_COMMIT();
}

template <typename CT>
__global__ __launch_bounds__(256, 1) void gemm_mma_f16(
        const __half* __restrict__ Ah, const __half* __restrict__ Bh,
        CT* __restrict__ C, int M, int N, int K) {
    extern __shared__ char dsm[];
    const uint32_t sb = smem_u32(dsm);
    const int tid  = threadIdx.x;
    const int lane = tid & 31;
    const int wid  = tid >> 5;
    const int wm = (wid >> 2) * 64;       // 0 / 64
    const int wn = (wid & 3) * 64;        // 0..192

    const int a_r  = lane & 15;
    const int a_g0 = lane >> 4;
    const int b_r  = (lane & 7) + ((lane >> 4) << 3);
    const int b_g0 = (lane >> 3) & 1;
    const int fr = lane >> 2;
    const int fc = (lane & 3) * 2;

    const int ntn = N >> 8;
    const int ntiles = (M >> 7) * ntn;
    const int NC = K / 64;

    for (int t = blockIdx.x; t < ntiles; t += gridDim.x) {
        const int m0 = (t / ntn) << 7;
        const int n0 = (t % ntn) << 8;

        float acc[4][8][4];
#pragma unroll
        for (int i = 0; i < 4; i++)
#pragma unroll
            for (int j = 0; j < 8; j++)
#pragma unroll
                for (int r = 0; r < 4; r++) acc[i][j][r] = 0.f;

        stage_copies(tid, m0, n0, 0,  K, sb,        Ah, Bh);
        stage_copies(tid, m0, n0, 64, K, sb + STGB, Ah, Bh);

        uint32_t st = sb;
        for (int c = 0; c < NC; c++) {
            CP_WAIT1();
            __syncthreads();
            if (c + 2 < NC)
                stage_copies(tid, m0, n0, (c + 2) * 64, K,
                             sb + ((c + 2) % NSTG) * STGB, Ah, Bh);
            else
                CP_COMMIT();

#pragma unroll
            for (int kk = 0; kk < 4; kk++) {
                const int gbase = kk * 2;
                uint32_t ah[4][4];
#pragma unroll
                for (int mf = 0; mf < 4; mf++) {
                    uint32_t ad = st + gswz(wm + mf * 16 + a_r, gbase + a_g0);
                    LDSM4(ah[mf][0], ah[mf][1], ah[mf][2], ah[mf][3], ad);
                }
                uint32_t bh[8][2];
#pragma unroll
                for (int ng = 0; ng < 4; ng++) {
                    uint32_t bd = st + ABUF + gswz(wn + ng * 16 + b_r, gbase + b_g0);
                    uint32_t t0, t1, t2, t3;
                    LDSM4(t0, t1, t2, t3, bd);
                    bh[2 * ng][0] = t0; bh[2 * ng][1] = t1;
                    bh[2 * ng + 1][0] = t2; bh[2 * ng + 1][1] = t3;
                }
#pragma unroll
                for (int mf = 0; mf < 4; mf++)
#pragma unroll
                    for (int nf = 0; nf < 8; nf++)
                        MMA16816(acc[mf][nf], ah[mf], bh[nf][0], bh[nf][1]);
            }
            st += STGB;
            if (st == sb + NSTG * STGB) st = sb;
        }

#pragma unroll
        for (int mf = 0; mf < 4; mf++) {
#pragma unroll
            for (int nf = 0; nf < 8; nf++) {
                CT* p0 = C + (size_t)(m0 + wm + mf * 16 + fr) * N + n0 + wn + nf * 8 + fc;
                CT* p1 = p0 + 8 * N;
                if (sizeof(CT) == 2) {
                    __half2 h0 = __floats2half2_rn(acc[mf][nf][0], acc[mf][nf][1]);
                    __half2 h1 = __floats2half2_rn(acc[mf][nf][2], acc[mf][nf][3]);
                    *(__half2*)p0 = h0;
                    *(__half2*)p1 = h1;
                } else {
                    p0[0] = (CT)acc[mf][nf][0]; p0[1] = (CT)acc[mf][nf][1];
                    p1[0] = (CT)acc[mf][nf][2]; p1[1] = (CT)acc[mf][nf][3];
                }
            }
        }
        __syncthreads();
    }
}

// ---------------------------------------------------------------------------
// RoPE on fp16 qkv, vectorized (2 j per thread).
// ---------------------------------------------------------------------------
#define LN1E4_OVER_64 0.14391156f

__global__ __launch_bounds__(256) void rope_kernel(const __half* __restrict__ qkv,
                                                   const int* __restrict__ positions,
                                                   __half* __restrict__ qh,
                                                   __half* __restrict__ kh) {
    int idx = blockIdx.x * blockDim.x + threadIdx.x;
    const int total = BB * SS * NH * 32;
    if (idx >= total) return;
    int jp = (idx & 31) * 2;
    int h  = (idx >> 5) & 31;
    int t  = idx >> 10;
    int pos = positions[t];

    float a0 = (float)pos * __expf(-(float)jp * LN1E4_OVER_64);
    float a1 = (float)pos * __expf(-(float)(jp + 1) * LN1E4_OVER_64);
    float s0, c0, s1, c1;
    __sincosf(a0, &s0, &c0);
    __sincosf(a1, &s1, &c1);

    size_t base = (size_t)t * THID + h * HD;
    size_t obase = (size_t)t * HID + h * HD;
    {
        __half2 x1 = *(const __half2*)(qkv + base + jp);
        __half2 x2 = *(const __half2*)(qkv + base + HALF + jp);
        float x1a = __half2float(x1.x), x1b = __half2float(x1.y);
        float x2a = __half2float(x2.x), x2b = __half2float(x2.y);
        *(__half2*)(qh + obase + jp) =
            __floats2half2_rn((x1a * c0 - x2a * s0) * SCALING,
                              (x1b * c1 - x2b * s1) * SCALING);
        *(__half2*)(qh + obase + HALF + jp) =
            __floats2half2_rn((x2a * c0 + x1a * s0) * SCALING,
                              (x2b * c1 + x1b * s1) * SCALING);
    }
    {
        size_t kb = base + HID;
        __half2 x1 = *(const __half2*)(qkv + kb + jp);
        __half2 x2 = *(const __half2*)(qkv + kb + HALF + jp);
        float x1a = __half2float(x1.x), x1b = __half2float(x1.y);
        float x2a = __half2float(x2.x), x2b = __half2float(x2.y);
        *(__half2*)(kh + obase + jp) =
            __floats2half2_rn(x1a * c0 - x2a * s0, x1b * c1 - x2b * s1);
        *(__half2*)(kh + obase + HALF + jp) =
            __floats2half2_rn(x2a * c0 + x1a * s0, x2b * c1 + x1b * s1);
    }
}

// ---------------------------------------------------------------------------
// Flash attention on HMMA. BM=64 (128 threads), 3-stage K/V ring. (R14)
// ---------------------------------------------------------------------------
#define FSM_Q   0
#define FSM_KV  16384
#define FSTG    32768
#define FLASH_DYN (16384 + 3 * FSTG)

__device__ __forceinline__ void flash_load_kv(uint32_t kdst, uint32_t vdst,
                                              int tid, int tok0,
                                              const __half* kh, const __half* qkvh,
                                              int h) {
#pragma unroll
    for (int i = 0; i < 8; i++) {
        int idx = tid + i * 128;
        int row = idx >> 4, g = idx & 15;
        int tok = tok0 + row;
        CP16(kdst + vswz(row, g), kh + ((size_t)tok * HID + h * HD + g * 8));
        CP16(vdst + vswz(row, g),
             qkvh + ((size_t)tok * THID + 2 * HID + h * HD + g * 8));
    }
    CP_COMMIT();
}

__global__ __launch_bounds__(128, 2) void flash_hmma(const __half* __restrict__ qh,
                                                     const __half* __restrict__ kh,
                                                     const __half* __restrict__ qkvh,
                                                     __half* __restrict__ ah) {
    const int qt = blockIdx.x;
    const int h  = blockIdx.y;
    const int b  = blockIdx.z;

    extern __shared__ char dsm[];
    const uint32_t sb = smem_u32(dsm);
    const int tid  = threadIdx.x;
    const int lane = tid & 31;
    const int wid  = tid >> 5;
    const int fr = lane >> 2;
    const int qq = lane & 3;

    const int a_r  = lane & 15;
    const int a_gh = lane >> 4;
    const int b_r  = (lane & 7) + ((lane >> 4) << 3);
    const int b_gh = (lane >> 3) & 1;
    const int vk   = (lane & 7) + (((lane >> 3) & 1) << 3);
    const int vg   = lane >> 4;

#pragma unroll
    for (int i = 0; i < 8; i++) {
        int idx = tid + i * 128;
        int row = idx >> 4, g = idx & 15;
        const __half* src = qh + ((size_t)(b * SS + qt * 64 + row) * HID + h * HD + g * 8);
        CP16(sb + FSM_Q + vswz(row, g), src);
    }
    CP_COMMIT();

    flash_load_kv(sb + FSM_KV, sb + FSM_KV + 16384, tid, b * SS, kh, qkvh, h);
    if (qt >= 1)
        flash_load_kv(sb + FSM_KV + FSTG, sb + FSM_KV + FSTG + 16384,
                      tid, b * SS + 64, kh, qkvh, h);
    else
        CP_COMMIT();

    float o[16][4];
#pragma unroll
    for (int i = 0; i < 16; i++)
#pragma unroll
        for (int r = 0; r < 4; r++) o[i][r] = 0.f;
    float m0 = -1e30f, m1 = -1e30f, l0 = 0.f, l1 = 0.f;

    for (int j = 0; j <= qt; j++) {
        if (j + 2 <= qt) {
            uint32_t base = sb + FSM_KV + ((j + 2) % 3) * FSTG;
            flash_load_kv(base, base + 16384, tid, b * SS + (j + 2) * 64, kh, qkvh, h);
        } else {
            CP_COMMIT();
        }
        CP_WAIT2();
        __syncthreads();

        const uint32_t kbuf = sb + FSM_KV + (j % 3) * FSTG;
        const uint32_t vbuf = kbuf + 16384;

        float s[8][4];
#pragma unroll
        for (int nf = 0; nf < 8; nf++)
#pragma unroll
            for (int r = 0; r < 4; r++) s[nf][r] = 0.f;

#pragma unroll
        for (int ks = 0; ks < 8; ks++) {
            uint32_t aq[4];
            LDSM4(aq[0], aq[1], aq[2], aq[3],
                  sb + FSM_Q + vswz(wid * 16 + a_r, ks * 2 + a_gh));
#pragma unroll
            for (int np = 0; np < 4; np++) {
                uint32_t t0, t1, t2, t3;
                LDSM4(t0, t1, t2, t3, kbuf + vswz(np * 16 + b_r, ks * 2 + b_gh));
                MMA16816(s[np * 2],     aq, t0, t1);
                MMA16816(s[np * 2 + 1], aq, t2, t3);
            }
        }

        if (j == qt) {
            int row0 = wid * 16 + fr;
            int row1 = row0 + 8;
#pragma unroll
            for (int nf = 0; nf < 8; nf++) {
                int c0 = nf * 8 + qq * 2;
                if (c0 > row0)     s[nf][0] = -1e30f;
                if (c0 + 1 > row0) s[nf][1] = -1e30f;
                if (c0 > row1)     s[nf][2] = -1e30f;
                if (c0 + 1 > row1) s[nf][3] = -1e30f;
            }
        }

        float mx0 = -1e30f, mx1 = -1e30f;
#pragma unroll
        for (int nf = 0; nf < 8; nf++) {
            mx0 = fmaxf(mx0, fmaxf(s[nf][0], s[nf][1]));
            mx1 = fmaxf(mx1, fmaxf(s[nf][2], s[nf][3]));
        }
        mx0 = fmaxf(mx0, __shfl_xor_sync(0xffffffffu, mx0, 1));
        mx0 = fmaxf(mx0, __shfl_xor_sync(0xffffffffu, mx0, 2));
        mx1 = fmaxf(mx1, __shfl_xor_sync(0xffffffffu, mx1, 1));
        mx1 = fmaxf(mx1, __shfl_xor_sync(0xffffffffu, mx1, 2));

        float mn0 = fmaxf(m0, mx0), mn1 = fmaxf(m1, mx1);
        float f0 = __expf(m0 - mn0), f1 = __expf(m1 - mn1);
        m0 = mn0; m1 = mn1;

        uint32_t ph[8][2];
        float sum0 = 0.f, sum1 = 0.f;
#pragma unroll
        for (int nf = 0; nf < 8; nf++) {
            float p0 = __expf(s[nf][0] - m0);
            float p1 = __expf(s[nf][1] - m0);
            float p2 = __expf(s[nf][2] - m1);
            float p3 = __expf(s[nf][3] - m1);
            sum0 += p0 + p1; sum1 += p2 + p3;
            __half2 h01 = __floats2half2_rn(p0, p1);
            __half2 h23 = __floats2half2_rn(p2, p3);
            ph[nf][0] = *(uint32_t*)&h01;
            ph[nf][1] = *(uint32_t*)&h23;
        }
        sum0 += __shfl_xor_sync(0xffffffffu, sum0, 1);
        sum0 += __shfl_xor_sync(0xffffffffu, sum0, 2);
        sum1 += __shfl_xor_sync(0xffffffffu, sum1, 1);
        sum1 += __shfl_xor_sync(0xffffffffu, sum1, 2);
        l0 = l0 * f0 + sum0;
        l1 = l1 * f1 + sum1;

#pragma unroll
        for (int i = 0; i < 16; i++) {
            o[i][0] *= f0; o[i][1] *= f0;
            o[i][2] *= f1; o[i][3] *= f1;
        }

#pragma unroll
        for (int ks = 0; ks < 4; ks++) {
            uint32_t ap[4] = {ph[2 * ks][0], ph[2 * ks][1],
                              ph[2 * ks + 1][0], ph[2 * ks + 1][1]};
#pragma unroll
            for (int np = 0; np < 8; np++) {
                uint32_t t0, t1, t2, t3;
                LDSM4T(t0, t1, t2, t3, vbuf + vswz(ks * 16 + vk, np * 2 + vg));
                MMA16816(o[np * 2],     ap, t0, t1);
                MMA16816(o[np * 2 + 1], ap, t2, t3);
            }
        }
    }

    float inv0 = 1.f / l0, inv1 = 1.f / l1;
    int row0 = b * SS + qt * 64 + wid * 16 + fr;
#pragma unroll
    for (int np = 0; np < 16; np++) {
        int col = h * HD + np * 8 + qq * 2;
        __half2 v0 = __floats2half2_rn(o[np][0] * inv0, o[np][1] * inv0);
        __half2 v1 = __floats2half2_rn(o[np][2] * inv1, o[np][3] * inv1);
        *(__half2*)(ah + (size_t)row0 * HID + col) = v0;
        *(__half2*)(ah + (size_t)(row0 + 8) * HID + col) = v1;
    }
}

// ---------------------------------------------------------------------------
extern "C" void kernel_launch(void* const* d_in, const int* in_sizes, int n_in,
                              void* d_out, int out_size) {
    const int*   positions = (const int*)  d_in[0];
    const float* hidden    = (const float*)d_in[1];
    const float* Wqkv      = (const float*)d_in[2];
    const float* Wo        = (const float*)d_in[3];
    float* out = (float*)d_out;

    __half *qkvh, *hh, *ah, *qh, *oh, *qhx, *khx;
    cudaGetSymbolAddress((void**)&qkvh, g_qkv_h);
    cudaGetSymbolAddress((void**)&hh, g_hid_h);
    cudaGetSymbolAddress((void**)&ah, g_attn_h);
    cudaGetSymbolAddress((void**)&qh, g_wqkv_h);
    cudaGetSymbolAddress((void**)&oh, g_wo_h);
    cudaGetSymbolAddress((void**)&qhx, g_q_h);
    cudaGetSymbolAddress((void**)&khx, g_k_h);

    int smCount = 148;
    cudaDeviceGetAttribute(&smCount, cudaDevAttrMultiProcessorCount, 0);

    cudaFuncSetAttribute(gemm_mma_f16<__half>,
                         cudaFuncAttributeMaxDynamicSharedMemorySize, GEMM_DYN);
    cudaFuncSetAttribute(gemm_mma_f16<float>,
                         cudaFuncAttributeMaxDynamicSharedMemorySize, GEMM_DYN);
    cudaFuncSetAttribute(flash_hmma,
                         cudaFuncAttributeMaxDynamicSharedMemorySize, FLASH_DYN);

    {
        size_t n4 = (size_t)MTOK * HID / 4;
        convert_h<<<(unsigned)((n4 + 255) / 256), 256>>>(hidden, hh, n4);
    }
    transpose_h<<<dim3(THID / 64, HID / 32), 256>>>(Wqkv, qh, HID, THID);
    gemm_mma_f16<__half><<<smCount, 256, GEMM_DYN>>>(hh, qh, qkvh, MTOK, THID, HID);
    {
        int total = BB * SS * NH * 32;
        rope_kernel<<<(total + 255) / 256, 256>>>(qkvh, positions, qhx, khx);
    }
    flash_hmma<<<dim3(SS / 64, NH, BB), 128, FLASH_DYN>>>(qhx, khx, qkvh, ah);
    transpose_h<<<dim3(HID / 64, HID / 32), 256>>>(Wo, oh, HID, HID);
    gemm_mma_f16<float><<<smCount, 256, GEMM_DYN>>>(ah, oh, out, MTOK, HID, HID);
}

// round 16
// speedup vs baseline: 1.0476x; 1.0476x over previous
#include <cuda_runtime.h>
#include <cuda_fp16.h>
#include <math.h>
#include <stdint.h>

#define HID   4096
#define NH    32
#define HD    128
#define HALF  64
#define BB    2
#define SS    2048
#define THID  12288
#define MTOK  (BB*SS)
#define SCALING 0.08838834764831845f

// ---------------- scratch ----------------------------------------------------
__device__ __half g_qkv_h[(size_t)MTOK * THID];
__device__ __half g_q_h [(size_t)MTOK * HID];
__device__ __half g_k_h [(size_t)MTOK * HID];
__device__ __half g_hid_h [(size_t)MTOK * HID];
__device__ __half g_attn_h[(size_t)MTOK * HID];
__device__ __half g_wqkv_h[(size_t)THID * HID];  // transposed [N][K]
__device__ __half g_wo_h  [(size_t)HID * HID];   // transposed [N][K]

// ---------------------------- asm helpers -----------------------------------
__device__ __forceinline__ uint32_t smem_u32(const void* p) {
    uint32_t a;
    asm("{ .reg .u64 t; cvta.to.shared.u64 t, %1; cvt.u32.u64 %0, t; }" : "=r"(a) : "l"(p));
    return a;
}
#define CP16(dst, src)  asm volatile("cp.async.cg.shared.global [%0], [%1], 16;" :: "r"(dst), "l"(src) : "memory")
#define CP_COMMIT()     asm volatile("cp.async.commit_group;" ::: "memory")
#define CP_WAIT1()      asm volatile("cp.async.wait_group 1;" ::: "memory")
#define CP_WAIT2()      asm volatile("cp.async.wait_group 2;" ::: "memory")

#define LDSM4(r0,r1,r2,r3,addr)                                                \
    asm volatile("ldmatrix.sync.aligned.m8n8.x4.shared.b16 {%0,%1,%2,%3}, [%4];" \
        : "=r"(r0),"=r"(r1),"=r"(r2),"=r"(r3) : "r"(addr))

#define LDSM4T(r0,r1,r2,r3,addr)                                               \
    asm volatile("ldmatrix.sync.aligned.m8n8.x4.trans.shared.b16 {%0,%1,%2,%3}, [%4];" \
        : "=r"(r0),"=r"(r1),"=r"(r2),"=r"(r3) : "r"(addr))

#define MMA16816(c,a,b0,b1)                                                    \
    asm volatile("mma.sync.aligned.m16n8k16.row.col.f32.f16.f16.f32 "          \
        "{%0,%1,%2,%3},{%4,%5,%6,%7},{%8,%9},{%0,%1,%2,%3};"                   \
        : "+f"((c)[0]),"+f"((c)[1]),"+f"((c)[2]),"+f"((c)[3])                  \
        : "r"((a)[0]),"r"((a)[1]),"r"((a)[2]),"r"((a)[3]),"r"(b0),"r"(b1))

// 128B-row swizzle (8 x 16B granules, XOR with row&7)
__device__ __forceinline__ uint32_t gswz(int row, int g) {
    return (uint32_t)(row * 128 + ((g ^ (row & 7)) << 4));
}
// 256B-row variant for the flash tiles.
__device__ __forceinline__ uint32_t vswz(int row, int g) {
    return (uint32_t)(row * 256 + ((g ^ (row & 7)) << 4));
}

// ---------------------------------------------------------------------------
__global__ __launch_bounds__(256) void convert_h(const float* __restrict__ in,
                                                 __half* __restrict__ hi, size_t n4) {
    size_t i = (size_t)blockIdx.x * blockDim.x + threadIdx.x;
    if (i >= n4) return;
    float4 v = ((const float4*)in)[i];
    __half h[4] = {__float2half(v.x), __float2half(v.y),
                   __float2half(v.z), __float2half(v.w)};
    ((uint2*)hi)[i] = *(uint2*)h;
}

// ---------------------------------------------------------------------------
// Transpose + fp16: B[K][N] fp32 -> Bt [N][K].  32k x 64n tiles.
// ---------------------------------------------------------------------------
__global__ __launch_bounds__(256) void transpose_h(const float* __restrict__ B,
                                                   __half* __restrict__ th,
                                                   int K, int N) {
    __shared__ float tile[32][65];
    const int n0 = blockIdx.x * 64, k0 = blockIdx.y * 32;
#pragma unroll
    for (int i = 0; i < 8; i++) {
        int idx = threadIdx.x + i * 256;
        int r = idx >> 6, c = idx & 63;
        tile[r][c] = B[(size_t)(k0 + r) * N + n0 + c];
    }
    __syncthreads();
#pragma unroll
    for (int i = 0; i < 4; i++) {
        int idx = threadIdx.x + i * 256;
        int n = idx >> 4, kp = idx & 15;
        __half2 v = __floats2half2_rn(tile[2 * kp][n], tile[2 * kp + 1][n]);
        *(__half2*)(th + (size_t)(n0 + n) * K + k0 + 2 * kp) = v;
    }
}

// ---------------------------------------------------------------------------
// Persistent fp16 GEMM on mma.sync. 128x128 tiles, BK=64, 3 stages x 32KB,
// 2 CTAs/SM, grid-stride tile loop. (R14 configuration)
// ---------------------------------------------------------------------------
#define BUFB  16384                // 128 rows x 128B
#define STGB  (2 * BUFB)
#define NSTG  3
#define GEMM_DYN (NSTG * STGB)

__device__ __forceinline__ void stage_copies(int tid, int m0, int n0, int kc, int K,
                                             uint32_t sbase,
                                             const __half* Ah, const __half* Bh) {
#pragma unroll
    for (int i = 0; i < 8; i++) {
        int id  = tid + i * 256;       // 0..2047
        int buf = id >> 10;            // 0..1
        int idx = id & 1023;
        int row = idx >> 3;            // 0..127
        int g   = idx & 7;
        uint32_t dst = sbase + buf * BUFB + gswz(row, g);
        const __half* src = (buf == 0) ? Ah + (size_t)(m0 + row) * K + kc + g * 8
                                       : Bh + (size_t)(n0 + row) * K + kc + g * 8;
        CP16(dst, src);
    }
    CP_COMMIT();
}

template <typename CT>
__global__ __launch_bounds__(256, 2) void gemm_mma_f16(
        const __half* __restrict__ Ah, const __half* __restrict__ Bh,
        CT* __restrict__ C, int M, int N, int K) {
    extern __shared__ char dsm[];
    const uint32_t sb = smem_u32(dsm);
    const int tid  = threadIdx.x;
    const int lane = tid & 31;
    const int wid  = tid >> 5;
    const int wm = (wid >> 2) * 64;
    const int wn = (wid & 3) * 32;

    const int a_r  = lane & 15;
    const int a_g0 = lane >> 4;
    const int b_r  = (lane & 7) + ((lane >> 4) << 3);
    const int b_g0 = (lane >> 3) & 1;
    const int fr = lane >> 2;
    const int fc = (lane & 3) * 2;

    const int ntn = N >> 7;
    const int ntiles = (M >> 7) * ntn;
    const int NC = K / 64;

    for (int t = blockIdx.x; t < ntiles; t += gridDim.x) {
        const int m0 = (t / ntn) << 7;
        const int n0 = (t % ntn) << 7;

        float acc[4][4][4];
#pragma unroll
        for (int i = 0; i < 4; i++)
#pragma unroll
            for (int j = 0; j < 4; j++)
#pragma unroll
                for (int r = 0; r < 4; r++) acc[i][j][r] = 0.f;

        stage_copies(tid, m0, n0, 0,  K, sb,        Ah, Bh);
        stage_copies(tid, m0, n0, 64, K, sb + STGB, Ah, Bh);

        uint32_t st = sb;
        for (int c = 0; c < NC; c++) {
            CP_WAIT1();
            __syncthreads();
            if (c + 2 < NC)
                stage_copies(tid, m0, n0, (c + 2) * 64, K,
                             sb + ((c + 2) % NSTG) * STGB, Ah, Bh);
            else
                CP_COMMIT();

#pragma unroll
            for (int kk = 0; kk < 4; kk++) {
                const int gbase = kk * 2;
                uint32_t ah[4][4];
#pragma unroll
                for (int mf = 0; mf < 4; mf++) {
                    uint32_t ad = st + gswz(wm + mf * 16 + a_r, gbase + a_g0);
                    LDSM4(ah[mf][0], ah[mf][1], ah[mf][2], ah[mf][3], ad);
                }
                uint32_t bh[4][2];
#pragma unroll
                for (int ng = 0; ng < 2; ng++) {
                    uint32_t bd = st + BUFB + gswz(wn + ng * 16 + b_r, gbase + b_g0);
                    uint32_t t0, t1, t2, t3;
                    LDSM4(t0, t1, t2, t3, bd);
                    bh[2 * ng][0] = t0; bh[2 * ng][1] = t1;
                    bh[2 * ng + 1][0] = t2; bh[2 * ng + 1][1] = t3;
                }
#pragma unroll
                for (int mf = 0; mf < 4; mf++)
#pragma unroll
                    for (int nf = 0; nf < 4; nf++)
                        MMA16816(acc[mf][nf], ah[mf], bh[nf][0], bh[nf][1]);
            }
            st += STGB;
            if (st == sb + NSTG * STGB) st = sb;
        }

#pragma unroll
        for (int mf = 0; mf < 4; mf++) {
#pragma unroll
            for (int nf = 0; nf < 4; nf++) {
                CT* p0 = C + (size_t)(m0 + wm + mf * 16 + fr) * N + n0 + wn + nf * 8 + fc;
                CT* p1 = p0 + 8 * N;
                if (sizeof(CT) == 2) {
                    __half2 h0 = __floats2half2_rn(acc[mf][nf][0], acc[mf][nf][1]);
                    __half2 h1 = __floats2half2_rn(acc[mf][nf][2], acc[mf][nf][3]);
                    *(__half2*)p0 = h0;
                    *(__half2*)p1 = h1;
                } else {
                    *(float2*)p0 = make_float2(acc[mf][nf][0], acc[mf][nf][1]);
                    *(float2*)p1 = make_float2(acc[mf][nf][2], acc[mf][nf][3]);
                }
            }
        }
        __syncthreads();
    }
}

// ---------------------------------------------------------------------------
// RoPE on fp16 qkv, vectorized (2 j per thread).
// ---------------------------------------------------------------------------
#define LN1E4_OVER_64 0.14391156f

__global__ __launch_bounds__(256) void rope_kernel(const __half* __restrict__ qkv,
                                                   const int* __restrict__ positions,
                                                   __half* __restrict__ qh,
                                                   __half* __restrict__ kh) {
    int idx = blockIdx.x * blockDim.x + threadIdx.x;
    const int total = BB * SS * NH * 32;
    if (idx >= total) return;
    int jp = (idx & 31) * 2;
    int h  = (idx >> 5) & 31;
    int t  = idx >> 10;
    int pos = positions[t];

    float a0 = (float)pos * __expf(-(float)jp * LN1E4_OVER_64);
    float a1 = (float)pos * __expf(-(float)(jp + 1) * LN1E4_OVER_64);
    float s0, c0, s1, c1;
    __sincosf(a0, &s0, &c0);
    __sincosf(a1, &s1, &c1);

    size_t base = (size_t)t * THID + h * HD;
    size_t obase = (size_t)t * HID + h * HD;
    {
        __half2 x1 = *(const __half2*)(qkv + base + jp);
        __half2 x2 = *(const __half2*)(qkv + base + HALF + jp);
        float x1a = __half2float(x1.x), x1b = __half2float(x1.y);
        float x2a = __half2float(x2.x), x2b = __half2float(x2.y);
        *(__half2*)(qh + obase + jp) =
            __floats2half2_rn((x1a * c0 - x2a * s0) * SCALING,
                              (x1b * c1 - x2b * s1) * SCALING);
        *(__half2*)(qh + obase + HALF + jp) =
            __floats2half2_rn((x2a * c0 + x1a * s0) * SCALING,
                              (x2b * c1 + x1b * s1) * SCALING);
    }
    {
        size_t kb = base + HID;
        __half2 x1 = *(const __half2*)(qkv + kb + jp);
        __half2 x2 = *(const __half2*)(qkv + kb + HALF + jp);
        float x1a = __half2float(x1.x), x1b = __half2float(x1.y);
        float x2a = __half2float(x2.x), x2b = __half2float(x2.y);
        *(__half2*)(kh + obase + jp) =
            __floats2half2_rn(x1a * c0 - x2a * s0, x1b * c1 - x2b * s1);
        *(__half2*)(kh + obase + HALF + jp) =
            __floats2half2_rn(x2a * c0 + x1a * s0, x2b * c1 + x1b * s1);
    }
}

// ---------------------------------------------------------------------------
// Flash attention on HMMA. BM=64 (128 threads), 3-stage K/V ring.
// Longest-first scheduling: qt = nqt-1-blockIdx.x.
// ---------------------------------------------------------------------------
#define FSM_Q   0
#define FSM_KV  16384
#define FSTG    32768
#define FLASH_DYN (16384 + 3 * FSTG)

__device__ __forceinline__ void flash_load_kv(uint32_t kdst, uint32_t vdst,
                                              int tid, int tok0,
                                              const __half* kh, const __half* qkvh,
                                              int h) {
#pragma unroll
    for (int i = 0; i < 8; i++) {
        int idx = tid + i * 128;
        int row = idx >> 4, g = idx & 15;
        int tok = tok0 + row;
        CP16(kdst + vswz(row, g), kh + ((size_t)tok * HID + h * HD + g * 8));
        CP16(vdst + vswz(row, g),
             qkvh + ((size_t)tok * THID + 2 * HID + h * HD + g * 8));
    }
    CP_COMMIT();
}

__global__ __launch_bounds__(128, 2) void flash_hmma(const __half* __restrict__ qh,
                                                     const __half* __restrict__ kh,
                                                     const __half* __restrict__ qkvh,
                                                     __half* __restrict__ ah) {
    const int qt = gridDim.x - 1 - blockIdx.x;   // longest CTAs first
    const int h  = blockIdx.y;
    const int b  = blockIdx.z;

    extern __shared__ char dsm[];
    const uint32_t sb = smem_u32(dsm);
    const int tid  = threadIdx.x;
    const int lane = tid & 31;
    const int wid  = tid >> 5;
    const int fr = lane >> 2;
    const int qq = lane & 3;

    const int a_r  = lane & 15;
    const int a_gh = lane >> 4;
    const int b_r  = (lane & 7) + ((lane >> 4) << 3);
    const int b_gh = (lane >> 3) & 1;
    const int vk   = (lane & 7) + (((lane >> 3) & 1) << 3);
    const int vg   = lane >> 4;

#pragma unroll
    for (int i = 0; i < 8; i++) {
        int idx = tid + i * 128;
        int row = idx >> 4, g = idx & 15;
        const __half* src = qh + ((size_t)(b * SS + qt * 64 + row) * HID + h * HD + g * 8);
        CP16(sb + FSM_Q + vswz(row, g), src);
    }
    CP_COMMIT();

    flash_load_kv(sb + FSM_KV, sb + FSM_KV + 16384, tid, b * SS, kh, qkvh, h);
    if (qt >= 1)
        flash_load_kv(sb + FSM_KV + FSTG, sb + FSM_KV + FSTG + 16384,
                      tid, b * SS + 64, kh, qkvh, h);
    else
        CP_COMMIT();

    float o[16][4];
#pragma unroll
    for (int i = 0; i < 16; i++)
#pragma unroll
        for (int r = 0; r < 4; r++) o[i][r] = 0.f;
    float m0 = -1e30f, m1 = -1e30f, l0 = 0.f, l1 = 0.f;

    for (int j = 0; j <= qt; j++) {
        if (j + 2 <= qt) {
            uint32_t base = sb + FSM_KV + ((j + 2) % 3) * FSTG;
            flash_load_kv(base, base + 16384, tid, b * SS + (j + 2) * 64, kh, qkvh, h);
        } else {
            CP_COMMIT();
        }
        CP_WAIT2();
        __syncthreads();

        const uint32_t kbuf = sb + FSM_KV + (j % 3) * FSTG;
        const uint32_t vbuf = kbuf + 16384;

        float s[8][4];
#pragma unroll
        for (int nf = 0; nf < 8; nf++)
#pragma unroll
            for (int r = 0; r < 4; r++) s[nf][r] = 0.f;

#pragma unroll
        for (int ks = 0; ks < 8; ks++) {
            uint32_t aq[4];
            LDSM4(aq[0], aq[1], aq[2], aq[3],
                  sb + FSM_Q + vswz(wid * 16 + a_r, ks * 2 + a_gh));
#pragma unroll
            for (int np = 0; np < 4; np++) {
                uint32_t t0, t1, t2, t3;
                LDSM4(t0, t1, t2, t3, kbuf + vswz(np * 16 + b_r, ks * 2 + b_gh));
                MMA16816(s[np * 2],     aq, t0, t1);
                MMA16816(s[np * 2 + 1], aq, t2, t3);
            }
        }

        if (j == qt) {
            int row0 = wid * 16 + fr;
            int row1 = row0 + 8;
#pragma unroll
            for (int nf = 0; nf < 8; nf++) {
                int c0 = nf * 8 + qq * 2;
                if (c0 > row0)     s[nf][0] = -1e30f;
                if (c0 + 1 > row0) s[nf][1] = -1e30f;
                if (c0 > row1)     s[nf][2] = -1e30f;
                if (c0 + 1 > row1) s[nf][3] = -1e30f;
            }
        }

        float mx0 = -1e30f, mx1 = -1e30f;
#pragma unroll
        for (int nf = 0; nf < 8; nf++) {
            mx0 = fmaxf(mx0, fmaxf(s[nf][0], s[nf][1]));
            mx1 = fmaxf(mx1, fmaxf(s[nf][2], s[nf][3]));
        }
        mx0 = fmaxf(mx0, __shfl_xor_sync(0xffffffffu, mx0, 1));
        mx0 = fmaxf(mx0, __shfl_xor_sync(0xffffffffu, mx0, 2));
        mx1 = fmaxf(mx1, __shfl_xor_sync(0xffffffffu, mx1, 1));
        mx1 = fmaxf(mx1, __shfl_xor_sync(0xffffffffu, mx1, 2));

        float mn0 = fmaxf(m0, mx0), mn1 = fmaxf(m1, mx1);
        float f0 = __expf(m0 - mn0), f1 = __expf(m1 - mn1);
        m0 = mn0; m1 = mn1;

        uint32_t ph[8][2];
        float sum0 = 0.f, sum1 = 0.f;
#pragma unroll
        for (int nf = 0; nf < 8; nf++) {
            float p0 = __expf(s[nf][0] - m0);
            float p1 = __expf(s[nf][1] - m0);
            float p2 = __expf(s[nf][2] - m1);
            float p3 = __expf(s[nf][3] - m1);
            sum0 += p0 + p1; sum1 += p2 + p3;
            __half2 h01 = __floats2half2_rn(p0, p1);
            __half2 h23 = __floats2half2_rn(p2, p3);
            ph[nf][0] = *(uint32_t*)&h01;
            ph[nf][1] = *(uint32_t*)&h23;
        }
        sum0 += __shfl_xor_sync(0xffffffffu, sum0, 1);
        sum0 += __shfl_xor_sync(0xffffffffu, sum0, 2);
        sum1 += __shfl_xor_sync(0xffffffffu, sum1, 1);
        sum1 += __shfl_xor_sync(0xffffffffu, sum1, 2);
        l0 = l0 * f0 + sum0;
        l1 = l1 * f1 + sum1;

#pragma unroll
        for (int i = 0; i < 16; i++) {
            o[i][0] *= f0; o[i][1] *= f0;
            o[i][2] *= f1; o[i][3] *= f1;
        }

#pragma unroll
        for (int ks = 0; ks < 4; ks++) {
            uint32_t ap[4] = {ph[2 * ks][0], ph[2 * ks][1],
                              ph[2 * ks + 1][0], ph[2 * ks + 1][1]};
#pragma unroll
            for (int np = 0; np < 8; np++) {
                uint32_t t0, t1, t2, t3;
                LDSM4T(t0, t1, t2, t3, vbuf + vswz(ks * 16 + vk, np * 2 + vg));
                MMA16816(o[np * 2],     ap, t0, t1);
                MMA16816(o[np * 2 + 1], ap, t2, t3);
            }
        }
    }

    float inv0 = 1.f / l0, inv1 = 1.f / l1;
    int row0 = b * SS + qt * 64 + wid * 16 + fr;
#pragma unroll
    for (int np = 0; np < 16; np++) {
        int col = h * HD + np * 8 + qq * 2;
        __half2 v0 = __floats2half2_rn(o[np][0] * inv0, o[np][1] * inv0);
        __half2 v1 = __floats2half2_rn(o[np][2] * inv1, o[np][3] * inv1);
        *(__half2*)(ah + (size_t)row0 * HID + col) = v0;
        *(__half2*)(ah + (size_t)(row0 + 8) * HID + col) = v1;
    }
}

// ---------------------------------------------------------------------------
extern "C" void kernel_launch(void* const* d_in, const int* in_sizes, int n_in,
                              void* d_out, int out_size) {
    const int*   positions = (const int*)  d_in[0];
    const float* hidden    = (const float*)d_in[1];
    const float* Wqkv      = (const float*)d_in[2];
    const float* Wo        = (const float*)d_in[3];
    float* out = (float*)d_out;

    __half *qkvh, *hh, *ah, *qh, *oh, *qhx, *khx;
    cudaGetSymbolAddress((void**)&qkvh, g_qkv_h);
    cudaGetSymbolAddress((void**)&hh, g_hid_h);
    cudaGetSymbolAddress((void**)&ah, g_attn_h);
    cudaGetSymbolAddress((void**)&qh, g_wqkv_h);
    cudaGetSymbolAddress((void**)&oh, g_wo_h);
    cudaGetSymbolAddress((void**)&qhx, g_q_h);
    cudaGetSymbolAddress((void**)&khx, g_k_h);

    int smCount = 148;
    cudaDeviceGetAttribute(&smCount, cudaDevAttrMultiProcessorCount, 0);
    const int pgrid = 2 * smCount;

    cudaFuncSetAttribute(gemm_mma_f16<__half>,
                         cudaFuncAttributeMaxDynamicSharedMemorySize, GEMM_DYN);
    cudaFuncSetAttribute(gemm_mma_f16<float>,
                         cudaFuncAttributeMaxDynamicSharedMemorySize, GEMM_DYN);
    cudaFuncSetAttribute(flash_hmma,
                         cudaFuncAttributeMaxDynamicSharedMemorySize, FLASH_DYN);

    {
        size_t n4 = (size_t)MTOK * HID / 4;
        convert_h<<<(unsigned)((n4 + 255) / 256), 256>>>(hidden, hh, n4);
    }
    transpose_h<<<dim3(THID / 64, HID / 32), 256>>>(Wqkv, qh, HID, THID);
    gemm_mma_f16<__half><<<pgrid, 256, GEMM_DYN>>>(hh, qh, qkvh, MTOK, THID, HID);
    {
        int total = BB * SS * NH * 32;
        rope_kernel<<<(total + 255) / 256, 256>>>(qkvh, positions, qhx, khx);
    }
    flash_hmma<<<dim3(SS / 64, NH, BB), 128, FLASH_DYN>>>(qhx, khx, qkvh, ah);
    transpose_h<<<dim3(HID / 64, HID / 32), 256>>>(Wo, oh, HID, HID);
    gemm_mma_f16<float><<<pgrid, 256, GEMM_DYN>>>(ah, oh, out, MTOK, HID, HID);
}

// round 17
// speedup vs baseline: 1.0480x; 1.0004x over previous
#include <cuda_runtime.h>
#include <cuda_fp16.h>
#include <math.h>
#include <stdint.h>

#define HID   4096
#define NH    32
#define HD    128
#define HALF  64
#define BB    2
#define SS    2048
#define THID  12288
#define MTOK  (BB*SS)
#define SCALING 0.08838834764831845f

// ---------------- scratch ----------------------------------------------------
__device__ __half g_qkv_h[(size_t)MTOK * THID];
__device__ __half g_q_h [(size_t)MTOK * HID];
__device__ __half g_k_h [(size_t)MTOK * HID];
__device__ __half g_hid_h [(size_t)MTOK * HID];
__device__ __half g_attn_h[(size_t)MTOK * HID];
__device__ __half g_wqkv_h[(size_t)THID * HID];  // transposed [N][K]
__device__ __half g_wo_h  [(size_t)HID * HID];   // transposed [N][K]

// ---------------------------- asm helpers -----------------------------------
__device__ __forceinline__ uint32_t smem_u32(const void* p) {
    uint32_t a;
    asm("{ .reg .u64 t; cvta.to.shared.u64 t, %1; cvt.u32.u64 %0, t; }" : "=r"(a) : "l"(p));
    return a;
}
#define CP16(dst, src)  asm volatile("cp.async.cg.shared.global [%0], [%1], 16;" :: "r"(dst), "l"(src) : "memory")
#define CP_COMMIT()     asm volatile("cp.async.commit_group;" ::: "memory")
#define CP_WAIT1()      asm volatile("cp.async.wait_group 1;" ::: "memory")
#define CP_WAIT2()      asm volatile("cp.async.wait_group 2;" ::: "memory")

#define LDSM4(r0,r1,r2,r3,addr)                                                \
    asm volatile("ldmatrix.sync.aligned.m8n8.x4.shared.b16 {%0,%1,%2,%3}, [%4];" \
        : "=r"(r0),"=r"(r1),"=r"(r2),"=r"(r3) : "r"(addr))

#define LDSM4T(r0,r1,r2,r3,addr)                                               \
    asm volatile("ldmatrix.sync.aligned.m8n8.x4.trans.shared.b16 {%0,%1,%2,%3}, [%4];" \
        : "=r"(r0),"=r"(r1),"=r"(r2),"=r"(r3) : "r"(addr))

#define MMA16816(c,a,b0,b1)                                                    \
    asm volatile("mma.sync.aligned.m16n8k16.row.col.f32.f16.f16.f32 "          \
        "{%0,%1,%2,%3},{%4,%5,%6,%7},{%8,%9},{%0,%1,%2,%3};"                   \
        : "+f"((c)[0]),"+f"((c)[1]),"+f"((c)[2]),"+f"((c)[3])                  \
        : "r"((a)[0]),"r"((a)[1]),"r"((a)[2]),"r"((a)[3]),"r"(b0),"r"(b1))

// 128B-row swizzle (8 x 16B granules, XOR with row&7)
__device__ __forceinline__ uint32_t gswz(int row, int g) {
    return (uint32_t)(row * 128 + ((g ^ (row & 7)) << 4));
}
// 256B-row variant for the flash tiles.
__device__ __forceinline__ uint32_t vswz(int row, int g) {
    return (uint32_t)(row * 256 + ((g ^ (row & 7)) << 4));
}

// ---------------------------------------------------------------------------
// Combined prep: convert hidden fp32->fp16, transpose Wqkv, transpose Wo.
// 1D grid split: [0,16384) convert, [16384,40960) Wqkv, [40960,49152) Wo.
// ---------------------------------------------------------------------------
#define PREP_CONV_BLKS  16384
#define PREP_WQKV_BLKS  24576      // (12288/64) x (4096/32)
#define PREP_WO_BLKS    8192       // (4096/64)  x (4096/32)
#define PREP_BLKS       (PREP_CONV_BLKS + PREP_WQKV_BLKS + PREP_WO_BLKS)

__device__ __forceinline__ void do_transpose(const float* __restrict__ B,
                                             __half* __restrict__ th,
                                             int K, int N, int bx, int by,
                                             float (*tile)[65]) {
    const int n0 = bx * 64, k0 = by * 32;
#pragma unroll
    for (int i = 0; i < 8; i++) {
        int idx = threadIdx.x + i * 256;
        int r = idx >> 6, c = idx & 63;
        tile[r][c] = B[(size_t)(k0 + r) * N + n0 + c];
    }
    __syncthreads();
#pragma unroll
    for (int i = 0; i < 4; i++) {
        int idx = threadIdx.x + i * 256;
        int n = idx >> 4, kp = idx & 15;
        __half2 v = __floats2half2_rn(tile[2 * kp][n], tile[2 * kp + 1][n]);
        *(__half2*)(th + (size_t)(n0 + n) * K + k0 + 2 * kp) = v;
    }
}

__global__ __launch_bounds__(256) void prep_kernel(const float* __restrict__ hidden,
                                                   const float* __restrict__ Wqkv,
                                                   const float* __restrict__ Wo,
                                                   __half* __restrict__ hh,
                                                   __half* __restrict__ qh,
                                                   __half* __restrict__ oh) {
    __shared__ float tile[32][65];
    int bid = blockIdx.x;
    if (bid < PREP_CONV_BLKS) {
        size_t i = (size_t)bid * 256 + threadIdx.x;   // one float4 per thread
        float4 v = ((const float4*)hidden)[i];
        __half h[4] = {__float2half(v.x), __float2half(v.y),
                       __float2half(v.z), __float2half(v.w)};
        ((uint2*)hh)[i] = *(uint2*)h;
    } else if (bid < PREP_CONV_BLKS + PREP_WQKV_BLKS) {
        int b = bid - PREP_CONV_BLKS;
        do_transpose(Wqkv, qh, HID, THID, b % (THID / 64), b / (THID / 64), tile);
    } else {
        int b = bid - PREP_CONV_BLKS - PREP_WQKV_BLKS;
        do_transpose(Wo, oh, HID, HID, b % (HID / 64), b / (HID / 64), tile);
    }
}

// ---------------------------------------------------------------------------
// Persistent fp16 GEMM on mma.sync. 128x128 tiles, BK=64, 3 stages x 32KB,
// 2 CTAs/SM, grid-stride tile loop. (R14/R16 configuration)
// ---------------------------------------------------------------------------
#define BUFB  16384                // 128 rows x 128B
#define STGB  (2 * BUFB)
#define NSTG  3
#define GEMM_DYN (NSTG * STGB)

__device__ __forceinline__ void stage_copies(int tid, int m0, int n0, int kc, int K,
                                             uint32_t sbase,
                                             const __half* Ah, const __half* Bh) {
#pragma unroll
    for (int i = 0; i < 8; i++) {
        int id  = tid + i * 256;       // 0..2047
        int buf = id >> 10;            // 0..1
        int idx = id & 1023;
        int row = idx >> 3;            // 0..127
        int g   = idx & 7;
        uint32_t dst = sbase + buf * BUFB + gswz(row, g);
        const __half* src = (buf == 0) ? Ah + (size_t)(m0 + row) * K + kc + g * 8
                                       : Bh + (size_t)(n0 + row) * K + kc + g * 8;
        CP16(dst, src);
    }
    CP_COMMIT();
}

template <typename CT>
__global__ __launch_bounds__(256, 2) void gemm_mma_f16(
        const __half* __restrict__ Ah, const __half* __restrict__ Bh,
        CT* __restrict__ C, int M, int N, int K) {
    extern __shared__ char dsm[];
    const uint32_t sb = smem_u32(dsm);
    const int tid  = threadIdx.x;
    const int lane = tid & 31;
    const int wid  = tid >> 5;
    const int wm = (wid >> 2) * 64;
    const int wn = (wid & 3) * 32;

    const int a_r  = lane & 15;
    const int a_g0 = lane >> 4;
    const int b_r  = (lane & 7) + ((lane >> 4) << 3);
    const int b_g0 = (lane >> 3) & 1;
    const int fr = lane >> 2;
    const int fc = (lane & 3) * 2;

    const int ntn = N >> 7;
    const int ntiles = (M >> 7) * ntn;
    const int NC = K / 64;

    for (int t = blockIdx.x; t < ntiles; t += gridDim.x) {
        const int m0 = (t / ntn) << 7;
        const int n0 = (t % ntn) << 7;

        float acc[4][4][4];
#pragma unroll
        for (int i = 0; i < 4; i++)
#pragma unroll
            for (int j = 0; j < 4; j++)
#pragma unroll
                for (int r = 0; r < 4; r++) acc[i][j][r] = 0.f;

        stage_copies(tid, m0, n0, 0,  K, sb,        Ah, Bh);
        stage_copies(tid, m0, n0, 64, K, sb + STGB, Ah, Bh);

        uint32_t st = sb;
        for (int c = 0; c < NC; c++) {
            CP_WAIT1();
            __syncthreads();
            if (c + 2 < NC)
                stage_copies(tid, m0, n0, (c + 2) * 64, K,
                             sb + ((c + 2) % NSTG) * STGB, Ah, Bh);
            else
                CP_COMMIT();

#pragma unroll
            for (int kk = 0; kk < 4; kk++) {
                const int gbase = kk * 2;
                uint32_t ah[4][4];
#pragma unroll
                for (int mf = 0; mf < 4; mf++) {
                    uint32_t ad = st + gswz(wm + mf * 16 + a_r, gbase + a_g0);
                    LDSM4(ah[mf][0], ah[mf][1], ah[mf][2], ah[mf][3], ad);
                }
                uint32_t bh[4][2];
#pragma unroll
                for (int ng = 0; ng < 2; ng++) {
                    uint32_t bd = st + BUFB + gswz(wn + ng * 16 + b_r, gbase + b_g0);
                    uint32_t t0, t1, t2, t3;
                    LDSM4(t0, t1, t2, t3, bd);
                    bh[2 * ng][0] = t0; bh[2 * ng][1] = t1;
                    bh[2 * ng + 1][0] = t2; bh[2 * ng + 1][1] = t3;
                }
#pragma unroll
                for (int mf = 0; mf < 4; mf++)
#pragma unroll
                    for (int nf = 0; nf < 4; nf++)
                        MMA16816(acc[mf][nf], ah[mf], bh[nf][0], bh[nf][1]);
            }
            st += STGB;
            if (st == sb + NSTG * STGB) st = sb;
        }

#pragma unroll
        for (int mf = 0; mf < 4; mf++) {
#pragma unroll
            for (int nf = 0; nf < 4; nf++) {
                CT* p0 = C + (size_t)(m0 + wm + mf * 16 + fr) * N + n0 + wn + nf * 8 + fc;
                CT* p1 = p0 + 8 * N;
                if (sizeof(CT) == 2) {
                    __half2 h0 = __floats2half2_rn(acc[mf][nf][0], acc[mf][nf][1]);
                    __half2 h1 = __floats2half2_rn(acc[mf][nf][2], acc[mf][nf][3]);
                    *(__half2*)p0 = h0;
                    *(__half2*)p1 = h1;
                } else {
                    *(float2*)p0 = make_float2(acc[mf][nf][0], acc[mf][nf][1]);
                    *(float2*)p1 = make_float2(acc[mf][nf][2], acc[mf][nf][3]);
                }
            }
        }
        __syncthreads();
    }
}

// ---------------------------------------------------------------------------
// RoPE on fp16 qkv, vectorized (2 j per thread).
// ---------------------------------------------------------------------------
#define LN1E4_OVER_64 0.14391156f

__global__ __launch_bounds__(256) void rope_kernel(const __half* __restrict__ qkv,
                                                   const int* __restrict__ positions,
                                                   __half* __restrict__ qh,
                                                   __half* __restrict__ kh) {
    int idx = blockIdx.x * blockDim.x + threadIdx.x;
    const int total = BB * SS * NH * 32;
    if (idx >= total) return;
    int jp = (idx & 31) * 2;
    int h  = (idx >> 5) & 31;
    int t  = idx >> 10;
    int pos = positions[t];

    float a0 = (float)pos * __expf(-(float)jp * LN1E4_OVER_64);
    float a1 = (float)pos * __expf(-(float)(jp + 1) * LN1E4_OVER_64);
    float s0, c0, s1, c1;
    __sincosf(a0, &s0, &c0);
    __sincosf(a1, &s1, &c1);

    size_t base = (size_t)t * THID + h * HD;
    size_t obase = (size_t)t * HID + h * HD;
    {
        __half2 x1 = *(const __half2*)(qkv + base + jp);
        __half2 x2 = *(const __half2*)(qkv + base + HALF + jp);
        float x1a = __half2float(x1.x), x1b = __half2float(x1.y);
        float x2a = __half2float(x2.x), x2b = __half2float(x2.y);
        *(__half2*)(qh + obase + jp) =
            __floats2half2_rn((x1a * c0 - x2a * s0) * SCALING,
                              (x1b * c1 - x2b * s1) * SCALING);
        *(__half2*)(qh + obase + HALF + jp) =
            __floats2half2_rn((x2a * c0 + x1a * s0) * SCALING,
                              (x2b * c1 + x1b * s1) * SCALING);
    }
    {
        size_t kb = base + HID;
        __half2 x1 = *(const __half2*)(qkv + kb + jp);
        __half2 x2 = *(const __half2*)(qkv + kb + HALF + jp);
        float x1a = __half2float(x1.x), x1b = __half2float(x1.y);
        float x2a = __half2float(x2.x), x2b = __half2float(x2.y);
        *(__half2*)(kh + obase + jp) =
            __floats2half2_rn(x1a * c0 - x2a * s0, x1b * c1 - x2b * s1);
        *(__half2*)(kh + obase + HALF + jp) =
            __floats2half2_rn(x2a * c0 + x1a * s0, x2b * c1 + x1b * s1);
    }
}

// ---------------------------------------------------------------------------
// Flash attention on HMMA. BM=64 (128 threads), 3-stage K/V ring,
// longest-first scheduling. (R16 configuration)
// ---------------------------------------------------------------------------
#define FSM_Q   0
#define FSM_KV  16384
#define FSTG    32768
#define FLASH_DYN (16384 + 3 * FSTG)

__device__ __forceinline__ void flash_load_kv(uint32_t kdst, uint32_t vdst,
                                              int tid, int tok0,
                                              const __half* kh, const __half* qkvh,
                                              int h) {
#pragma unroll
    for (int i = 0; i < 8; i++) {
        int idx = tid + i * 128;
        int row = idx >> 4, g = idx & 15;
        int tok = tok0 + row;
        CP16(kdst + vswz(row, g), kh + ((size_t)tok * HID + h * HD + g * 8));
        CP16(vdst + vswz(row, g),
             qkvh + ((size_t)tok * THID + 2 * HID + h * HD + g * 8));
    }
    CP_COMMIT();
}

__global__ __launch_bounds__(128, 2) void flash_hmma(const __half* __restrict__ qh,
                                                     const __half* __restrict__ kh,
                                                     const __half* __restrict__ qkvh,
                                                     __half* __restrict__ ah) {
    const int qt = gridDim.x - 1 - blockIdx.x;
    const int h  = blockIdx.y;
    const int b  = blockIdx.z;

    extern __shared__ char dsm[];
    const uint32_t sb = smem_u32(dsm);
    const int tid  = threadIdx.x;
    const int lane = tid & 31;
    const int wid  = tid >> 5;
    const int fr = lane >> 2;
    const int qq = lane & 3;

    const int a_r  = lane & 15;
    const int a_gh = lane >> 4;
    const int b_r  = (lane & 7) + ((lane >> 4) << 3);
    const int b_gh = (lane >> 3) & 1;
    const int vk   = (lane & 7) + (((lane >> 3) & 1) << 3);
    const int vg   = lane >> 4;

#pragma unroll
    for (int i = 0; i < 8; i++) {
        int idx = tid + i * 128;
        int row = idx >> 4, g = idx & 15;
        const __half* src = qh + ((size_t)(b * SS + qt * 64 + row) * HID + h * HD + g * 8);
        CP16(sb + FSM_Q + vswz(row, g), src);
    }
    CP_COMMIT();

    flash_load_kv(sb + FSM_KV, sb + FSM_KV + 16384, tid, b * SS, kh, qkvh, h);
    if (qt >= 1)
        flash_load_kv(sb + FSM_KV + FSTG, sb + FSM_KV + FSTG + 16384,
                      tid, b * SS + 64, kh, qkvh, h);
    else
        CP_COMMIT();

    float o[16][4];
#pragma unroll
    for (int i = 0; i < 16; i++)
#pragma unroll
        for (int r = 0; r < 4; r++) o[i][r] = 0.f;
    float m0 = -1e30f, m1 = -1e30f, l0 = 0.f, l1 = 0.f;

    for (int j = 0; j <= qt; j++) {
        if (j + 2 <= qt) {
            uint32_t base = sb + FSM_KV + ((j + 2) % 3) * FSTG;
            flash_load_kv(base, base + 16384, tid, b * SS + (j + 2) * 64, kh, qkvh, h);
        } else {
            CP_COMMIT();
        }
        CP_WAIT2();
        __syncthreads();

        const uint32_t kbuf = sb + FSM_KV + (j % 3) * FSTG;
        const uint32_t vbuf = kbuf + 16384;

        float s[8][4];
#pragma unroll
        for (int nf = 0; nf < 8; nf++)
#pragma unroll
            for (int r = 0; r < 4; r++) s[nf][r] = 0.f;

#pragma unroll
        for (int ks = 0; ks < 8; ks++) {
            uint32_t aq[4];
            LDSM4(aq[0], aq[1], aq[2], aq[3],
                  sb + FSM_Q + vswz(wid * 16 + a_r, ks * 2 + a_gh));
#pragma unroll
            for (int np = 0; np < 4; np++) {
                uint32_t t0, t1, t2, t3;
                LDSM4(t0, t1, t2, t3, kbuf + vswz(np * 16 + b_r, ks * 2 + b_gh));
                MMA16816(s[np * 2],     aq, t0, t1);
                MMA16816(s[np * 2 + 1], aq, t2, t3);
            }
        }

        if (j == qt) {
            int row0 = wid * 16 + fr;
            int row1 = row0 + 8;
#pragma unroll
            for (int nf = 0; nf < 8; nf++) {
                int c0 = nf * 8 + qq * 2;
                if (c0 > row0)     s[nf][0] = -1e30f;
                if (c0 + 1 > row0) s[nf][1] = -1e30f;
                if (c0 > row1)     s[nf][2] = -1e30f;
                if (c0 + 1 > row1) s[nf][3] = -1e30f;
            }
        }

        float mx0 = -1e30f, mx1 = -1e30f;
#pragma unroll
        for (int nf = 0; nf < 8; nf++) {
            mx0 = fmaxf(mx0, fmaxf(s[nf][0], s[nf][1]));
            mx1 = fmaxf(mx1, fmaxf(s[nf][2], s[nf][3]));
        }
        mx0 = fmaxf(mx0, __shfl_xor_sync(0xffffffffu, mx0, 1));
        mx0 = fmaxf(mx0, __shfl_xor_sync(0xffffffffu, mx0, 2));
        mx1 = fmaxf(mx1, __shfl_xor_sync(0xffffffffu, mx1, 1));
        mx1 = fmaxf(mx1, __shfl_xor_sync(0xffffffffu, mx1, 2));

        float mn0 = fmaxf(m0, mx0), mn1 = fmaxf(m1, mx1);
        float f0 = __expf(m0 - mn0), f1 = __expf(m1 - mn1);
        m0 = mn0; m1 = mn1;

        uint32_t ph[8][2];
        float sum0 = 0.f, sum1 = 0.f;
#pragma unroll
        for (int nf = 0; nf < 8; nf++) {
            float p0 = __expf(s[nf][0] - m0);
            float p1 = __expf(s[nf][1] - m0);
            float p2 = __expf(s[nf][2] - m1);
            float p3 = __expf(s[nf][3] - m1);
            sum0 += p0 + p1; sum1 += p2 + p3;
            __half2 h01 = __floats2half2_rn(p0, p1);
            __half2 h23 = __floats2half2_rn(p2, p3);
            ph[nf][0] = *(uint32_t*)&h01;
            ph[nf][1] = *(uint32_t*)&h23;
        }
        sum0 += __shfl_xor_sync(0xffffffffu, sum0, 1);
        sum0 += __shfl_xor_sync(0xffffffffu, sum0, 2);
        sum1 += __shfl_xor_sync(0xffffffffu, sum1, 1);
        sum1 += __shfl_xor_sync(0xffffffffu, sum1, 2);
        l0 = l0 * f0 + sum0;
        l1 = l1 * f1 + sum1;

#pragma unroll
        for (int i = 0; i < 16; i++) {
            o[i][0] *= f0; o[i][1] *= f0;
            o[i][2] *= f1; o[i][3] *= f1;
        }

#pragma unroll
        for (int ks = 0; ks < 4; ks++) {
            uint32_t ap[4] = {ph[2 * ks][0], ph[2 * ks][1],
                              ph[2 * ks + 1][0], ph[2 * ks + 1][1]};
#pragma unroll
            for (int np = 0; np < 8; np++) {
                uint32_t t0, t1, t2, t3;
                LDSM4T(t0, t1, t2, t3, vbuf + vswz(ks * 16 + vk, np * 2 + vg));
                MMA16816(o[np * 2],     ap, t0, t1);
                MMA16816(o[np * 2 + 1], ap, t2, t3);
            }
        }
    }

    float inv0 = 1.f / l0, inv1 = 1.f / l1;
    int row0 = b * SS + qt * 64 + wid * 16 + fr;
#pragma unroll
    for (int np = 0; np < 16; np++) {
        int col = h * HD + np * 8 + qq * 2;
        __half2 v0 = __floats2half2_rn(o[np][0] * inv0, o[np][1] * inv0);
        __half2 v1 = __floats2half2_rn(o[np][2] * inv1, o[np][3] * inv1);
        *(__half2*)(ah + (size_t)row0 * HID + col) = v0;
        *(__half2*)(ah + (size_t)(row0 + 8) * HID + col) = v1;
    }
}

// ---------------------------------------------------------------------------
extern "C" void kernel_launch(void* const* d_in, const int* in_sizes, int n_in,
                              void* d_out, int out_size) {
    const int*   positions = (const int*)  d_in[0];
    const float* hidden    = (const float*)d_in[1];
    const float* Wqkv      = (const float*)d_in[2];
    const float* Wo        = (const float*)d_in[3];
    float* out = (float*)d_out;

    __half *qkvh, *hh, *ah, *qh, *oh, *qhx, *khx;
    cudaGetSymbolAddress((void**)&qkvh, g_qkv_h);
    cudaGetSymbolAddress((void**)&hh, g_hid_h);
    cudaGetSymbolAddress((void**)&ah, g_attn_h);
    cudaGetSymbolAddress((void**)&qh, g_wqkv_h);
    cudaGetSymbolAddress((void**)&oh, g_wo_h);
    cudaGetSymbolAddress((void**)&qhx, g_q_h);
    cudaGetSymbolAddress((void**)&khx, g_k_h);

    int smCount = 148;
    cudaDeviceGetAttribute(&smCount, cudaDevAttrMultiProcessorCount, 0);
    const int pgrid = 2 * smCount;

    cudaFuncSetAttribute(gemm_mma_f16<__half>,
                         cudaFuncAttributeMaxDynamicSharedMemorySize, GEMM_DYN);
    cudaFuncSetAttribute(gemm_mma_f16<float>,
                         cudaFuncAttributeMaxDynamicSharedMemorySize, GEMM_DYN);
    cudaFuncSetAttribute(flash_hmma,
                         cudaFuncAttributeMaxDynamicSharedMemorySize, FLASH_DYN);

    // 1) combined prep: hidden fp32->fp16, Wqkv^T, Wo^T
    prep_kernel<<<PREP_BLKS, 256>>>(hidden, Wqkv, Wo, hh, qh, oh);
    // 2) QKV projection
    gemm_mma_f16<__half><<<pgrid, 256, GEMM_DYN>>>(hh, qh, qkvh, MTOK, THID, HID);
    // 3) RoPE
    {
        int total = BB * SS * NH * 32;
        rope_kernel<<<(total + 255) / 256, 256>>>(qkvh, positions, qhx, khx);
    }
    // 4) Flash attention
    flash_hmma<<<dim3(SS / 64, NH, BB), 128, FLASH_DYN>>>(qhx, khx, qkvh, ah);
    // 5) Output projection
    gemm_mma_f16<float><<<pgrid, 256, GEMM_DYN>>>(ah, oh, out, MTOK, HID, HID);
}